// round 8
// baseline (speedup 1.0000x reference)
#include <cuda_runtime.h>
#include <math.h>

#define NMAT 256
#define D 64
#define DD 4096          // 64*64
#define DQ 68            // padded row stride (float4-aligned)
#define NSWEEP_OS 8      // one-sided Jacobi sweeps (7 insufficient; 8 proven)

// ---------------- device scratch (no allocations allowed) ----------------
__device__ float g_L[NMAT * DD];          // log(X) matrices        (4 MB)
__device__ float g_S[NMAT * DD];          // log(X) + M             (4 MB)
__device__ float g_gp[8 * NMAT * NMAT];   // split-K gram partials  (2 MB)
__device__ float g_W[NMAT * NMAT];        // kernel weights         (256 KB)
__device__ float g_sq[NMAT];
__device__ float g_s[NMAT];
__device__ float g_rs[NMAT];              // row sums
__device__ float g_cs[NMAT];              // col sums

// ========================================================================
// Kernel 1: one-sided Jacobi log, one WARP per matrix, columns in registers.
//   lane t holds column pair (a,b). Brent-Luk tournament via shuffles.
//   No __syncthreads in the rotation loop. At convergence columns are
//   lambda_i * v_i, so log X = sum_i (log(l_i)/l_i^2) g_i g_i^T.
//   Warp-uniform vote skips rotation work in converged rounds (late sweeps).
// ========================================================================
__global__ __launch_bounds__(32) void onesided_log_kernel(const float* __restrict__ X) {
    __shared__ float Gsm[D * DQ];   // columns (Gsm[r*DQ + col])
    __shared__ float Hsm[D * DQ];   // w_col * column

    const int m    = blockIdx.x;
    const int lane = threadIdx.x;
    const unsigned FULL = 0xffffffffu;
    const float* Xm = X + (size_t)m * DD;

    float a[D], b[D];

    // X is symmetric: column j == row j -> float4 row loads
    {
        const float4* ra = (const float4*)(Xm + (2 * lane)     * D);
        const float4* rb = (const float4*)(Xm + (2 * lane + 1) * D);
        #pragma unroll
        for (int t = 0; t < 16; ++t) {
            float4 v = ra[t];
            a[4*t+0] = v.x; a[4*t+1] = v.y; a[4*t+2] = v.z; a[4*t+3] = v.w;
            float4 w = rb[t];
            b[4*t+0] = w.x; b[4*t+1] = w.y; b[4*t+2] = w.z; b[4*t+3] = w.w;
        }
    }

    // initial column norms (tracked incrementally during sweeps)
    float na, nb;
    {
        float n0 = 0.f, n1 = 0.f, m0 = 0.f, m1 = 0.f;
        #pragma unroll
        for (int k = 0; k < D; k += 2) {
            n0 = fmaf(a[k], a[k], n0);     n1 = fmaf(a[k+1], a[k+1], n1);
            m0 = fmaf(b[k], b[k], m0);     m1 = fmaf(b[k+1], b[k+1], m1);
        }
        na = n0 + n1; nb = m0 + m1;
    }

    for (int sw = 0; sw < NSWEEP_OS; ++sw) {
        for (int rr = 0; rr < 63; ++rr) {
            // cross dot gamma = a . b  (4-way ILP)
            float g0 = 0.f, g1 = 0.f, g2 = 0.f, g3 = 0.f;
            #pragma unroll
            for (int k = 0; k < D; k += 4) {
                g0 = fmaf(a[k+0], b[k+0], g0);
                g1 = fmaf(a[k+1], b[k+1], g1);
                g2 = fmaf(a[k+2], b[k+2], g2);
                g3 = fmaf(a[k+3], b[k+3], g3);
            }
            float gam = (g0 + g1) + (g2 + g3);

            // warp-uniform early-out: all rotations in this round negligible
            bool conv = (gam * gam <= 1e-14f * na * nb);
            if (!__all_sync(FULL, conv)) {
                // rotation (each lane independent, no broadcast)
                float tau = (nb - na) / (2.0f * gam);
                float tt  = copysignf(1.0f, tau) / (fabsf(tau) + sqrtf(fmaf(tau, tau, 1.0f)));
                float c   = rsqrtf(fmaf(tt, tt, 1.0f));
                float s   = tt * c;
                if (gam == 0.0f) { c = 1.0f; s = 0.0f; }

                // rotate columns: a' = c a - s b ; b' = s a + c b
                float ns = -s;
                #pragma unroll
                for (int k = 0; k < D; ++k) {
                    float av = a[k], bv = b[k];
                    a[k] = fmaf(ns, bv, c * av);
                    b[k] = fmaf(s,  av, c * bv);
                }
                // norm tracking (exact rotation identities)
                float csg = 2.0f * c * s * gam;
                float cc2 = c * c, ss2 = s * s;
                float na_n = cc2 * na + ss2 * nb - csg;
                float nb_n = ss2 * na + cc2 * nb + csg;
                na = na_n; nb = nb_n;
            }

            // Brent-Luk permutation:
            //  a0 fixed; a1<-b0; a_i<-a_{i-1}; b_i<-b_{i+1}; b31<-a31
            {
                float tn  = (lane == 0) ? nb : na;
                float up  = __shfl_up_sync(FULL, tn, 1);
                float dn  = __shfl_down_sync(FULL, nb, 1);
                float na_o = na;
                na = (lane == 0)  ? na_o : up;
                nb = (lane == 31) ? na_o : dn;
            }
            #pragma unroll
            for (int k = 0; k < D; ++k) {
                float oa  = a[k];
                float tmp = (lane == 0) ? b[k] : oa;
                float up  = __shfl_up_sync(FULL, tmp, 1);
                float dn  = __shfl_down_sync(FULL, b[k], 1);
                a[k] = (lane == 0)  ? oa : up;
                b[k] = (lane == 31) ? oa : dn;
            }
        }
    }

    // exact final norms
    {
        float n0 = 0.f, n1 = 0.f, m0 = 0.f, m1 = 0.f;
        #pragma unroll
        for (int k = 0; k < D; k += 2) {
            n0 = fmaf(a[k], a[k], n0);     n1 = fmaf(a[k+1], a[k+1], n1);
            m0 = fmaf(b[k], b[k], m0);     m1 = fmaf(b[k+1], b[k+1], m1);
        }
        na = n0 + n1; nb = m0 + m1;
    }
    // weight = log(lambda)/lambda^2, lambda^2 = |g|^2
    float wa = 0.5f * logf(fmaxf(na, 1e-30f)) / na;
    float wb = 0.5f * logf(fmaxf(nb, 1e-30f)) / nb;

    // stash columns + scaled columns to smem
    {
        const int ia = 2 * lane, ib = 2 * lane + 1;
        #pragma unroll
        for (int r = 0; r < D; ++r) {
            Gsm[r * DQ + ia] = a[r];
            Hsm[r * DQ + ia] = wa * a[r];
            Gsm[r * DQ + ib] = b[r];
            Hsm[r * DQ + ib] = wb * b[r];
        }
    }
    __syncwarp();

    // L[r,c] = sum_i H[r,i] * G[c,i]; each lane computes rows 2*lane, 2*lane+1
    const int r0 = 2 * lane, r1 = 2 * lane + 1;
    #pragma unroll
    for (int t = 0; t < 16; ++t) {
        float4 h0 = *(const float4*)&Hsm[r0 * DQ + 4 * t];
        a[4*t+0] = h0.x; a[4*t+1] = h0.y; a[4*t+2] = h0.z; a[4*t+3] = h0.w;
        float4 h1 = *(const float4*)&Hsm[r1 * DQ + 4 * t];
        b[4*t+0] = h1.x; b[4*t+1] = h1.y; b[4*t+2] = h1.z; b[4*t+3] = h1.w;
    }

    float ssum = 0.f, sqsum = 0.f;
    float* o0 = g_L + (size_t)m * DD + r0 * D;
    float* o1 = g_L + (size_t)m * DD + r1 * D;
    for (int c4 = 0; c4 < D; c4 += 4) {
        float acc0[4] = {0.f, 0.f, 0.f, 0.f};
        float acc1[4] = {0.f, 0.f, 0.f, 0.f};
        #pragma unroll
        for (int cc = 0; cc < 4; ++cc) {
            const int c = c4 + cc;
            #pragma unroll
            for (int t = 0; t < 16; ++t) {
                float4 g = *(const float4*)&Gsm[c * DQ + 4 * t];  // broadcast
                acc0[cc] = fmaf(a[4*t+0], g.x, acc0[cc]);
                acc0[cc] = fmaf(a[4*t+1], g.y, acc0[cc]);
                acc0[cc] = fmaf(a[4*t+2], g.z, acc0[cc]);
                acc0[cc] = fmaf(a[4*t+3], g.w, acc0[cc]);
                acc1[cc] = fmaf(b[4*t+0], g.x, acc1[cc]);
                acc1[cc] = fmaf(b[4*t+1], g.y, acc1[cc]);
                acc1[cc] = fmaf(b[4*t+2], g.z, acc1[cc]);
                acc1[cc] = fmaf(b[4*t+3], g.w, acc1[cc]);
            }
        }
        *(float4*)&o0[c4] = make_float4(acc0[0], acc0[1], acc0[2], acc0[3]);
        *(float4*)&o1[c4] = make_float4(acc1[0], acc1[1], acc1[2], acc1[3]);
        #pragma unroll
        for (int cc = 0; cc < 4; ++cc) {
            ssum += acc0[cc] + acc1[cc];
            sqsum = fmaf(acc0[cc], acc0[cc], sqsum);
            sqsum = fmaf(acc1[cc], acc1[cc], sqsum);
        }
    }
    // warp reduce s / sq
    #pragma unroll
    for (int o = 16; o; o >>= 1) {
        ssum  += __shfl_down_sync(FULL, ssum,  o);
        sqsum += __shfl_down_sync(FULL, sqsum, o);
    }
    if (lane == 0) { g_s[m] = ssum; g_sq[m] = sqsum; }
}

// ========================================================================
// Kernel 2: gram partials  g_gp[z][i][j] = sum_{k in z-chunk} L[i][k] L[j][k]
// ========================================================================
__global__ __launch_bounds__(256) void gram_kernel() {
    __shared__ float As[64 * 17];
    __shared__ float Bs[64 * 17];
    const int bj = blockIdx.x, bi = blockIdx.y, bz = blockIdx.z;
    const int tid = threadIdx.x;
    const int ty = tid >> 4, tx = tid & 15;

    float acc[4][4];
    #pragma unroll
    for (int r = 0; r < 4; ++r)
        #pragma unroll
        for (int c = 0; c < 4; ++c) acc[r][c] = 0.0f;

    const int k0 = bz * 512;
    for (int kc = 0; kc < 512; kc += 16) {
        for (int l = tid; l < 1024; l += 256) {
            int r = l >> 4, kk = l & 15;
            As[r * 17 + kk] = g_L[(size_t)(bi * 64 + r) * DD + k0 + kc + kk];
            Bs[r * 17 + kk] = g_L[(size_t)(bj * 64 + r) * DD + k0 + kc + kk];
        }
        __syncthreads();
        #pragma unroll
        for (int kk = 0; kk < 16; ++kk) {
            float a[4], b[4];
            #pragma unroll
            for (int r = 0; r < 4; ++r) a[r] = As[(ty * 4 + r) * 17 + kk];
            #pragma unroll
            for (int c = 0; c < 4; ++c) b[c] = Bs[(tx * 4 + c) * 17 + kk];
            #pragma unroll
            for (int r = 0; r < 4; ++r)
                #pragma unroll
                for (int c = 0; c < 4; ++c)
                    acc[r][c] = fmaf(a[r], b[c], acc[r][c]);
        }
        __syncthreads();
    }
    #pragma unroll
    for (int r = 0; r < 4; ++r)
        #pragma unroll
        for (int c = 0; c < 4; ++c)
            g_gp[((size_t)bz * NMAT + bi * 64 + ty * 4 + r) * NMAT + bj * 64 + tx * 4 + c] = acc[r][c];
}

// ========================================================================
// Kernel 3: W = exp(-0.5 * pds / bw^2), fused row sums.  block = row i
// ========================================================================
__global__ __launch_bounds__(256) void w_kernel(const float* __restrict__ bwp) {
    __shared__ float red[8];
    const int i = blockIdx.x;
    const int j = threadIdx.x;

    float g = 0.0f;
    #pragma unroll
    for (int z = 0; z < 8; ++z)
        g += g_gp[((size_t)z * NMAT + i) * NMAT + j];

    const float bw  = bwp[0];
    const float inv = 0.5f / (bw * bw);
    const float eps = 1e-7f;
    float pds = g_sq[i] + g_sq[j] - 2.0f * g
              + 2.0f * eps * (g_s[j] - g_s[i])
              + eps * eps * 4096.0f;
    float wv = expf(-pds * inv);
    g_W[i * NMAT + j] = wv;

    float sum = wv;
    #pragma unroll
    for (int o = 16; o; o >>= 1) sum += __shfl_down_sync(0xffffffffu, sum, o);
    if ((j & 31) == 0) red[j >> 5] = sum;
    __syncthreads();
    if (j == 0) {
        float t = 0.0f;
        #pragma unroll
        for (int w = 0; w < 8; ++w) t += red[w];
        g_rs[i] = t;
    }
}

// col sums: 8 blocks x 256 threads, coalesced
__global__ __launch_bounds__(256) void colsum_kernel() {
    __shared__ float part[8][32];
    const int c0 = blockIdx.x * 32;
    const int c = threadIdx.x & 31;
    const int rchunk = threadIdx.x >> 5;
    float s = 0.0f;
    #pragma unroll
    for (int rr = 0; rr < 32; ++rr)
        s += g_W[(rchunk * 32 + rr) * NMAT + c0 + c];
    part[rchunk][c] = s;
    __syncthreads();
    if (threadIdx.x < 32) {
        float t = 0.0f;
        #pragma unroll
        for (int w = 0; w < 8; ++w) t += part[w][threadIdx.x];
        g_cs[c0 + threadIdx.x] = t;
    }
}

// ========================================================================
// Kernel 4: C = W^T L, fused mean-shift epilogue -> S = L_k + (C - cs_k L_k)/rs_k
// ========================================================================
__global__ __launch_bounds__(256) void ms_kernel() {
    __shared__ float Wt[16 * 65];
    __shared__ float Lt[16 * 65];
    const int bc = blockIdx.x;   // column tile
    const int bk = blockIdx.y;   // k (output row) tile
    const int tid = threadIdx.x;
    const int ty = tid >> 4, tx = tid & 15;

    float acc[4][4];
    #pragma unroll
    for (int r = 0; r < 4; ++r)
        #pragma unroll
        for (int c = 0; c < 4; ++c) acc[r][c] = 0.0f;

    for (int j0 = 0; j0 < NMAT; j0 += 16) {
        for (int l = tid; l < 1024; l += 256) {
            int jj = l >> 6, c = l & 63;
            Wt[jj * 65 + c] = g_W[(j0 + jj) * NMAT + bk * 64 + c];
            Lt[jj * 65 + c] = g_L[(size_t)(j0 + jj) * DD + bc * 64 + c];
        }
        __syncthreads();
        #pragma unroll
        for (int jj = 0; jj < 16; ++jj) {
            float a[4], b[4];
            #pragma unroll
            for (int r = 0; r < 4; ++r) a[r] = Wt[jj * 65 + ty * 4 + r];
            #pragma unroll
            for (int c = 0; c < 4; ++c) b[c] = Lt[jj * 65 + tx * 4 + c];
            #pragma unroll
            for (int r = 0; r < 4; ++r)
                #pragma unroll
                for (int c = 0; c < 4; ++c)
                    acc[r][c] = fmaf(a[r], b[c], acc[r][c]);
        }
        __syncthreads();
    }
    #pragma unroll
    for (int r = 0; r < 4; ++r) {
        int k = bk * 64 + ty * 4 + r;
        float rs = g_rs[k], cs = g_cs[k];
        float inv_rs = 1.0f / rs;
        #pragma unroll
        for (int c = 0; c < 4; ++c) {
            int col = bc * 64 + tx * 4 + c;
            float lk = g_L[(size_t)k * DD + col];
            g_S[(size_t)k * DD + col] = lk + (acc[r][c] - cs * lk) * inv_rs;
        }
    }
}

// ========================================================================
// Kernel 5: expm(S) via scaling-and-squaring + order-9 Horner Taylor
//   64 threads, row in registers (left operand), float4 smem loads
// ========================================================================
__global__ __launch_bounds__(64) void expm_kernel(float* __restrict__ out) {
    __shared__ float Bm[D * DQ];
    __shared__ float Q[D * DQ];
    __shared__ float redw[2];

    const int m = blockIdx.x;
    const int tid = threadIdx.x;

    float local = 0.0f;
    for (int l = tid; l < DD; l += 64) {
        float v = g_S[(size_t)m * DD + l];
        Bm[(l >> 6) * DQ + (l & 63)] = v;
        local = fmaf(v, v, local);
    }
    #pragma unroll
    for (int o = 16; o; o >>= 1) local += __shfl_down_sync(0xffffffffu, local, o);
    if ((tid & 31) == 0) redw[tid >> 5] = local;
    __syncthreads();

    float nf = sqrtf(redw[0] + redw[1]);
    int ksc = 0;
    if (nf > 0.5f) {
        ksc = (int)ceilf(log2f(nf * 2.0f));
        if (ksc > 15) ksc = 15;
        if (ksc < 0)  ksc = 0;
    }
    const float sc = exp2f((float)(-ksc));

    const int i = tid;
    // own (scaled) B row in registers; init Q = I
    float brow[D];
    #pragma unroll
    for (int t = 0; t < 16; ++t) {
        float4 v = *(const float4*)&Bm[i * DQ + 4 * t];
        brow[4*t+0] = v.x * sc; brow[4*t+1] = v.y * sc;
        brow[4*t+2] = v.z * sc; brow[4*t+3] = v.w * sc;
    }
    #pragma unroll
    for (int t = 0; t < 16; ++t) {
        float4 id = make_float4((4*t+0 == i) ? 1.f : 0.f, (4*t+1 == i) ? 1.f : 0.f,
                                (4*t+2 == i) ? 1.f : 0.f, (4*t+3 == i) ? 1.f : 0.f);
        *(float4*)&Q[i * DQ + 4 * t] = id;
    }
    __syncthreads();

    float rrow[D];

    // Horner: Q_{n-1} = I + (B * Q_n)/n, n = 9..1
    for (int n = 9; n >= 1; --n) {
        #pragma unroll
        for (int j = 0; j < D; ++j) rrow[j] = 0.0f;
        for (int k = 0; k < D; ++k) {
            float bv = brow[k];
            #pragma unroll
            for (int t = 0; t < 16; ++t) {
                float4 q = *(const float4*)&Q[k * DQ + 4 * t];  // broadcast
                rrow[4*t+0] = fmaf(bv, q.x, rrow[4*t+0]);
                rrow[4*t+1] = fmaf(bv, q.y, rrow[4*t+1]);
                rrow[4*t+2] = fmaf(bv, q.z, rrow[4*t+2]);
                rrow[4*t+3] = fmaf(bv, q.w, rrow[4*t+3]);
            }
        }
        __syncthreads();
        const float invn = 1.0f / (float)n;
        #pragma unroll
        for (int t = 0; t < 16; ++t) {
            float4 o4 = make_float4(
                rrow[4*t+0] * invn + ((4*t+0 == i) ? 1.f : 0.f),
                rrow[4*t+1] * invn + ((4*t+1 == i) ? 1.f : 0.f),
                rrow[4*t+2] * invn + ((4*t+2 == i) ? 1.f : 0.f),
                rrow[4*t+3] * invn + ((4*t+3 == i) ? 1.f : 0.f));
            *(float4*)&Q[i * DQ + 4 * t] = o4;
        }
        __syncthreads();
    }

    // repeated squaring
    for (int t2 = 0; t2 < ksc; ++t2) {
        #pragma unroll
        for (int t = 0; t < 16; ++t) {
            float4 v = *(const float4*)&Q[i * DQ + 4 * t];
            brow[4*t+0] = v.x; brow[4*t+1] = v.y; brow[4*t+2] = v.z; brow[4*t+3] = v.w;
        }
        #pragma unroll
        for (int j = 0; j < D; ++j) rrow[j] = 0.0f;
        for (int k = 0; k < D; ++k) {
            float bv = brow[k];
            #pragma unroll
            for (int t = 0; t < 16; ++t) {
                float4 q = *(const float4*)&Q[k * DQ + 4 * t];
                rrow[4*t+0] = fmaf(bv, q.x, rrow[4*t+0]);
                rrow[4*t+1] = fmaf(bv, q.y, rrow[4*t+1]);
                rrow[4*t+2] = fmaf(bv, q.z, rrow[4*t+2]);
                rrow[4*t+3] = fmaf(bv, q.w, rrow[4*t+3]);
            }
        }
        __syncthreads();
        #pragma unroll
        for (int t = 0; t < 16; ++t)
            *(float4*)&Q[i * DQ + 4 * t] =
                make_float4(rrow[4*t+0], rrow[4*t+1], rrow[4*t+2], rrow[4*t+3]);
        __syncthreads();
    }

    float* om = out + (size_t)m * DD + i * D;
    #pragma unroll
    for (int t = 0; t < 16; ++t) {
        float4 v = *(const float4*)&Q[i * DQ + 4 * t];
        *(float4*)&om[4 * t] = v;
    }
}

// ========================================================================
extern "C" void kernel_launch(void* const* d_in, const int* in_sizes, int n_in,
                              void* d_out, int out_size) {
    const float* X  = (const float*)d_in[0];
    const float* bw = (const float*)d_in[1];
    float* out = (float*)d_out;

    onesided_log_kernel<<<NMAT, 32>>>(X);
    gram_kernel<<<dim3(4, 4, 8), 256>>>();
    w_kernel<<<NMAT, 256>>>(bw);
    colsum_kernel<<<8, 256>>>();
    ms_kernel<<<dim3(64, 4), 256>>>();
    expm_kernel<<<NMAT, 64>>>(out);
}

// round 10
// speedup vs baseline: 1.0641x; 1.0641x over previous
#include <cuda_runtime.h>
#include <math.h>

#define NMAT 256
#define D 64
#define DD 4096          // 64*64
#define DQ 68            // padded row stride (float4-aligned)
#define NSWEEP_OS 8      // one-sided Jacobi sweeps (proven at 8; 6 fails)

// ---------------- device scratch (no allocations allowed) ----------------
__device__ float g_L[NMAT * DD];          // log(X) matrices        (4 MB)
__device__ float g_S[NMAT * DD];          // log(X) + M             (4 MB)
__device__ float g_gp[8 * NMAT * NMAT];   // split-K gram partials  (2 MB)
__device__ float g_W[NMAT * NMAT];        // kernel weights         (256 KB)
__device__ float g_sq[NMAT];
__device__ float g_s[NMAT];
__device__ float g_rs[NMAT];              // row sums
__device__ float g_cs[NMAT];              // col sums

// ========================================================================
// Kernel 1: one-sided Jacobi log, one WARP per matrix, columns in registers.
//   Tangent-form (scaled) rotations: lane holds UNNORMALIZED columns
//   (â, b̂) with per-column scales (sa, sb); a rotation is ONE fma per
//   element per column: â' = â − u·b̂, b̂' = b̂ + v·â,  sa*=c, sb*=c.
//   Renormalize once per sweep. True squared norms tracked exactly.
//   At convergence true columns are lambda_i*v_i:
//   log X = sum_i (log l_i / l_i^2) g_i g_i^T.
// ========================================================================
__global__ __launch_bounds__(32) void onesided_log_kernel(const float* __restrict__ X) {
    __shared__ float Gsm[D * DQ];   // columns (Gsm[r*DQ + col])
    __shared__ float Hsm[D * DQ];   // w_col * column

    const int m    = blockIdx.x;
    const int lane = threadIdx.x;
    const unsigned FULL = 0xffffffffu;
    const float* Xm = X + (size_t)m * DD;

    float a[D], b[D];

    // X is symmetric: column j == row j -> float4 row loads
    {
        const float4* ra = (const float4*)(Xm + (2 * lane)     * D);
        const float4* rb = (const float4*)(Xm + (2 * lane + 1) * D);
        #pragma unroll
        for (int t = 0; t < 16; ++t) {
            float4 v = ra[t];
            a[4*t+0] = v.x; a[4*t+1] = v.y; a[4*t+2] = v.z; a[4*t+3] = v.w;
            float4 w = rb[t];
            b[4*t+0] = w.x; b[4*t+1] = w.y; b[4*t+2] = w.z; b[4*t+3] = w.w;
        }
    }

    // true squared norms (tracked incrementally) + scales
    float na, nb, sa = 1.0f, sb = 1.0f;
    {
        float n0 = 0.f, n1 = 0.f, m0 = 0.f, m1 = 0.f;
        #pragma unroll
        for (int k = 0; k < D; k += 2) {
            n0 = fmaf(a[k], a[k], n0);     n1 = fmaf(a[k+1], a[k+1], n1);
            m0 = fmaf(b[k], b[k], m0);     m1 = fmaf(b[k+1], b[k+1], m1);
        }
        na = n0 + n1; nb = m0 + m1;
    }

    for (int sw = 0; sw < NSWEEP_OS; ++sw) {
        for (int rr = 0; rr < 63; ++rr) {
            // unnormalized cross dot (4-way ILP)
            float g0 = 0.f, g1 = 0.f, g2 = 0.f, g3 = 0.f;
            #pragma unroll
            for (int k = 0; k < D; k += 4) {
                g0 = fmaf(a[k+0], b[k+0], g0);
                g1 = fmaf(a[k+1], b[k+1], g1);
                g2 = fmaf(a[k+2], b[k+2], g2);
                g3 = fmaf(a[k+3], b[k+3], g3);
            }
            float ghat = (g0 + g1) + (g2 + g3);
            float gam  = sa * sb * ghat;          // true gamma

            if (gam != 0.0f) {
                float tau = (nb - na) / (2.0f * gam);
                float tt  = copysignf(1.0f, tau) / (fabsf(tau) + sqrtf(fmaf(tau, tau, 1.0f)));
                float c   = rsqrtf(fmaf(tt, tt, 1.0f));
                float s   = tt * c;

                float ratio = sb / sa;
                float u = tt * ratio;             // a' = a - u*b (unnormalized)
                float v = tt / ratio;             // b' = b + v*a

                #pragma unroll
                for (int k = 0; k < D; ++k) {
                    float av = a[k], bv = b[k];
                    a[k] = fmaf(-u, bv, av);
                    b[k] = fmaf( v, av, bv);
                }
                sa *= c; sb *= c;

                // true-norm tracking (exact rotation identities)
                float csg = 2.0f * c * s * gam;
                float cc2 = c * c, ss2 = s * s;
                float na_n = cc2 * na + ss2 * nb - csg;
                float nb_n = ss2 * na + cc2 * nb + csg;
                na = na_n; nb = nb_n;
            }

            // Brent-Luk permutation:
            //  a0 fixed; a1<-b0; a_i<-a_{i-1}; b_i<-b_{i+1}; b31<-a31
            {
                float tn, up, dn, o;
                o = na; tn = (lane == 0) ? nb : na;
                up = __shfl_up_sync(FULL, tn, 1);
                dn = __shfl_down_sync(FULL, nb, 1);
                na = (lane == 0)  ? o : up;
                nb = (lane == 31) ? o : dn;

                o = sa; tn = (lane == 0) ? sb : sa;
                up = __shfl_up_sync(FULL, tn, 1);
                dn = __shfl_down_sync(FULL, sb, 1);
                sa = (lane == 0)  ? o : up;
                sb = (lane == 31) ? o : dn;
            }
            #pragma unroll
            for (int k = 0; k < D; ++k) {
                float oa  = a[k];
                float tmp = (lane == 0) ? b[k] : oa;
                float up  = __shfl_up_sync(FULL, tmp, 1);
                float dn  = __shfl_down_sync(FULL, b[k], 1);
                a[k] = (lane == 0)  ? oa : up;
                b[k] = (lane == 31) ? oa : dn;
            }
        }

        // per-sweep renormalization (prevents scale drift / overflow)
        #pragma unroll
        for (int k = 0; k < D; ++k) { a[k] *= sa; b[k] *= sb; }
        sa = 1.0f; sb = 1.0f;
    }

    // exact final norms
    {
        float n0 = 0.f, n1 = 0.f, m0 = 0.f, m1 = 0.f;
        #pragma unroll
        for (int k = 0; k < D; k += 2) {
            n0 = fmaf(a[k], a[k], n0);     n1 = fmaf(a[k+1], a[k+1], n1);
            m0 = fmaf(b[k], b[k], m0);     m1 = fmaf(b[k+1], b[k+1], m1);
        }
        na = n0 + n1; nb = m0 + m1;
    }
    // weight = log(lambda)/lambda^2, lambda^2 = |g|^2
    float wa = 0.5f * logf(fmaxf(na, 1e-30f)) / na;
    float wb = 0.5f * logf(fmaxf(nb, 1e-30f)) / nb;

    // stash columns + scaled columns to smem
    {
        const int ia = 2 * lane, ib = 2 * lane + 1;
        #pragma unroll
        for (int r = 0; r < D; ++r) {
            Gsm[r * DQ + ia] = a[r];
            Hsm[r * DQ + ia] = wa * a[r];
            Gsm[r * DQ + ib] = b[r];
            Hsm[r * DQ + ib] = wb * b[r];
        }
    }
    __syncwarp();

    // L[r,c] = sum_i H[r,i] * G[c,i]; each lane computes rows 2*lane, 2*lane+1
    const int r0 = 2 * lane, r1 = 2 * lane + 1;
    #pragma unroll
    for (int t = 0; t < 16; ++t) {
        float4 h0 = *(const float4*)&Hsm[r0 * DQ + 4 * t];
        a[4*t+0] = h0.x; a[4*t+1] = h0.y; a[4*t+2] = h0.z; a[4*t+3] = h0.w;
        float4 h1 = *(const float4*)&Hsm[r1 * DQ + 4 * t];
        b[4*t+0] = h1.x; b[4*t+1] = h1.y; b[4*t+2] = h1.z; b[4*t+3] = h1.w;
    }

    float ssum = 0.f, sqsum = 0.f;
    float* o0 = g_L + (size_t)m * DD + r0 * D;
    float* o1 = g_L + (size_t)m * DD + r1 * D;
    for (int c4 = 0; c4 < D; c4 += 4) {
        float acc0[4] = {0.f, 0.f, 0.f, 0.f};
        float acc1[4] = {0.f, 0.f, 0.f, 0.f};
        #pragma unroll
        for (int cc = 0; cc < 4; ++cc) {
            const int c = c4 + cc;
            #pragma unroll
            for (int t = 0; t < 16; ++t) {
                float4 g = *(const float4*)&Gsm[c * DQ + 4 * t];  // broadcast
                acc0[cc] = fmaf(a[4*t+0], g.x, acc0[cc]);
                acc0[cc] = fmaf(a[4*t+1], g.y, acc0[cc]);
                acc0[cc] = fmaf(a[4*t+2], g.z, acc0[cc]);
                acc0[cc] = fmaf(a[4*t+3], g.w, acc0[cc]);
                acc1[cc] = fmaf(b[4*t+0], g.x, acc1[cc]);
                acc1[cc] = fmaf(b[4*t+1], g.y, acc1[cc]);
                acc1[cc] = fmaf(b[4*t+2], g.z, acc1[cc]);
                acc1[cc] = fmaf(b[4*t+3], g.w, acc1[cc]);
            }
        }
        *(float4*)&o0[c4] = make_float4(acc0[0], acc0[1], acc0[2], acc0[3]);
        *(float4*)&o1[c4] = make_float4(acc1[0], acc1[1], acc1[2], acc1[3]);
        #pragma unroll
        for (int cc = 0; cc < 4; ++cc) {
            ssum += acc0[cc] + acc1[cc];
            sqsum = fmaf(acc0[cc], acc0[cc], sqsum);
            sqsum = fmaf(acc1[cc], acc1[cc], sqsum);
        }
    }
    // warp reduce s / sq
    #pragma unroll
    for (int o = 16; o; o >>= 1) {
        ssum  += __shfl_down_sync(FULL, ssum,  o);
        sqsum += __shfl_down_sync(FULL, sqsum, o);
    }
    if (lane == 0) { g_s[m] = ssum; g_sq[m] = sqsum; }
}

// ========================================================================
// Kernel 2: gram partials  g_gp[z][i][j] = sum_{k in z-chunk} L[i][k] L[j][k]
// ========================================================================
__global__ __launch_bounds__(256) void gram_kernel() {
    __shared__ float As[64 * 17];
    __shared__ float Bs[64 * 17];
    const int bj = blockIdx.x, bi = blockIdx.y, bz = blockIdx.z;
    const int tid = threadIdx.x;
    const int ty = tid >> 4, tx = tid & 15;

    float acc[4][4];
    #pragma unroll
    for (int r = 0; r < 4; ++r)
        #pragma unroll
        for (int c = 0; c < 4; ++c) acc[r][c] = 0.0f;

    const int k0 = bz * 512;
    for (int kc = 0; kc < 512; kc += 16) {
        for (int l = tid; l < 1024; l += 256) {
            int r = l >> 4, kk = l & 15;
            As[r * 17 + kk] = g_L[(size_t)(bi * 64 + r) * DD + k0 + kc + kk];
            Bs[r * 17 + kk] = g_L[(size_t)(bj * 64 + r) * DD + k0 + kc + kk];
        }
        __syncthreads();
        #pragma unroll
        for (int kk = 0; kk < 16; ++kk) {
            float a[4], b[4];
            #pragma unroll
            for (int r = 0; r < 4; ++r) a[r] = As[(ty * 4 + r) * 17 + kk];
            #pragma unroll
            for (int c = 0; c < 4; ++c) b[c] = Bs[(tx * 4 + c) * 17 + kk];
            #pragma unroll
            for (int r = 0; r < 4; ++r)
                #pragma unroll
                for (int c = 0; c < 4; ++c)
                    acc[r][c] = fmaf(a[r], b[c], acc[r][c]);
        }
        __syncthreads();
    }
    #pragma unroll
    for (int r = 0; r < 4; ++r)
        #pragma unroll
        for (int c = 0; c < 4; ++c)
            g_gp[((size_t)bz * NMAT + bi * 64 + ty * 4 + r) * NMAT + bj * 64 + tx * 4 + c] = acc[r][c];
}

// ========================================================================
// Kernel 3: W = exp(-0.5 * pds / bw^2), fused row sums.  block = row i
// ========================================================================
__global__ __launch_bounds__(256) void w_kernel(const float* __restrict__ bwp) {
    __shared__ float red[8];
    const int i = blockIdx.x;
    const int j = threadIdx.x;

    float g = 0.0f;
    #pragma unroll
    for (int z = 0; z < 8; ++z)
        g += g_gp[((size_t)z * NMAT + i) * NMAT + j];

    const float bw  = bwp[0];
    const float inv = 0.5f / (bw * bw);
    const float eps = 1e-7f;
    float pds = g_sq[i] + g_sq[j] - 2.0f * g
              + 2.0f * eps * (g_s[j] - g_s[i])
              + eps * eps * 4096.0f;
    float wv = expf(-pds * inv);
    g_W[i * NMAT + j] = wv;

    float sum = wv;
    #pragma unroll
    for (int o = 16; o; o >>= 1) sum += __shfl_down_sync(0xffffffffu, sum, o);
    if ((j & 31) == 0) red[j >> 5] = sum;
    __syncthreads();
    if (j == 0) {
        float t = 0.0f;
        #pragma unroll
        for (int w = 0; w < 8; ++w) t += red[w];
        g_rs[i] = t;
    }
}

// col sums: 8 blocks x 256 threads, coalesced
__global__ __launch_bounds__(256) void colsum_kernel() {
    __shared__ float part[8][32];
    const int c0 = blockIdx.x * 32;
    const int c = threadIdx.x & 31;
    const int rchunk = threadIdx.x >> 5;
    float s = 0.0f;
    #pragma unroll
    for (int rr = 0; rr < 32; ++rr)
        s += g_W[(rchunk * 32 + rr) * NMAT + c0 + c];
    part[rchunk][c] = s;
    __syncthreads();
    if (threadIdx.x < 32) {
        float t = 0.0f;
        #pragma unroll
        for (int w = 0; w < 8; ++w) t += part[w][threadIdx.x];
        g_cs[c0 + threadIdx.x] = t;
    }
}

// ========================================================================
// Kernel 4: C = W^T L, fused mean-shift epilogue -> S = L_k + (C - cs_k L_k)/rs_k
// ========================================================================
__global__ __launch_bounds__(256) void ms_kernel() {
    __shared__ float Wt[16 * 65];
    __shared__ float Lt[16 * 65];
    const int bc = blockIdx.x;   // column tile
    const int bk = blockIdx.y;   // k (output row) tile
    const int tid = threadIdx.x;
    const int ty = tid >> 4, tx = tid & 15;

    float acc[4][4];
    #pragma unroll
    for (int r = 0; r < 4; ++r)
        #pragma unroll
        for (int c = 0; c < 4; ++c) acc[r][c] = 0.0f;

    for (int j0 = 0; j0 < NMAT; j0 += 16) {
        for (int l = tid; l < 1024; l += 256) {
            int jj = l >> 6, c = l & 63;
            Wt[jj * 65 + c] = g_W[(j0 + jj) * NMAT + bk * 64 + c];
            Lt[jj * 65 + c] = g_L[(size_t)(j0 + jj) * DD + bc * 64 + c];
        }
        __syncthreads();
        #pragma unroll
        for (int jj = 0; jj < 16; ++jj) {
            float a[4], b[4];
            #pragma unroll
            for (int r = 0; r < 4; ++r) a[r] = Wt[jj * 65 + ty * 4 + r];
            #pragma unroll
            for (int c = 0; c < 4; ++c) b[c] = Lt[jj * 65 + tx * 4 + c];
            #pragma unroll
            for (int r = 0; r < 4; ++r)
                #pragma unroll
                for (int c = 0; c < 4; ++c)
                    acc[r][c] = fmaf(a[r], b[c], acc[r][c]);
        }
        __syncthreads();
    }
    #pragma unroll
    for (int r = 0; r < 4; ++r) {
        int k = bk * 64 + ty * 4 + r;
        float rs = g_rs[k], cs = g_cs[k];
        float inv_rs = 1.0f / rs;
        #pragma unroll
        for (int c = 0; c < 4; ++c) {
            int col = bc * 64 + tx * 4 + c;
            float lk = g_L[(size_t)k * DD + col];
            g_S[(size_t)k * DD + col] = lk + (acc[r][c] - cs * lk) * inv_rs;
        }
    }
}

// ========================================================================
// Kernel 5: expm(S) via scaling-and-squaring + order-9 Horner Taylor
//   64 threads, row in registers (left operand), float4 smem loads
// ========================================================================
__global__ __launch_bounds__(64) void expm_kernel(float* __restrict__ out) {
    __shared__ float Bm[D * DQ];
    __shared__ float Q[D * DQ];
    __shared__ float redw[2];

    const int m = blockIdx.x;
    const int tid = threadIdx.x;

    float local = 0.0f;
    for (int l = tid; l < DD; l += 64) {
        float v = g_S[(size_t)m * DD + l];
        Bm[(l >> 6) * DQ + (l & 63)] = v;
        local = fmaf(v, v, local);
    }
    #pragma unroll
    for (int o = 16; o; o >>= 1) local += __shfl_down_sync(0xffffffffu, local, o);
    if ((tid & 31) == 0) redw[tid >> 5] = local;
    __syncthreads();

    float nf = sqrtf(redw[0] + redw[1]);
    int ksc = 0;
    if (nf > 0.5f) {
        ksc = (int)ceilf(log2f(nf * 2.0f));
        if (ksc > 15) ksc = 15;
        if (ksc < 0)  ksc = 0;
    }
    const float sc = exp2f((float)(-ksc));

    const int i = tid;
    // own (scaled) B row in registers; init Q = I
    float brow[D];
    #pragma unroll
    for (int t = 0; t < 16; ++t) {
        float4 v = *(const float4*)&Bm[i * DQ + 4 * t];
        brow[4*t+0] = v.x * sc; brow[4*t+1] = v.y * sc;
        brow[4*t+2] = v.z * sc; brow[4*t+3] = v.w * sc;
    }
    #pragma unroll
    for (int t = 0; t < 16; ++t) {
        float4 id = make_float4((4*t+0 == i) ? 1.f : 0.f, (4*t+1 == i) ? 1.f : 0.f,
                                (4*t+2 == i) ? 1.f : 0.f, (4*t+3 == i) ? 1.f : 0.f);
        *(float4*)&Q[i * DQ + 4 * t] = id;
    }
    __syncthreads();

    float rrow[D];

    // Horner: Q_{n-1} = I + (B * Q_n)/n, n = 9..1
    for (int n = 9; n >= 1; --n) {
        #pragma unroll
        for (int j = 0; j < D; ++j) rrow[j] = 0.0f;
        for (int k = 0; k < D; ++k) {
            float bv = brow[k];
            #pragma unroll
            for (int t = 0; t < 16; ++t) {
                float4 q = *(const float4*)&Q[k * DQ + 4 * t];  // broadcast
                rrow[4*t+0] = fmaf(bv, q.x, rrow[4*t+0]);
                rrow[4*t+1] = fmaf(bv, q.y, rrow[4*t+1]);
                rrow[4*t+2] = fmaf(bv, q.z, rrow[4*t+2]);
                rrow[4*t+3] = fmaf(bv, q.w, rrow[4*t+3]);
            }
        }
        __syncthreads();
        const float invn = 1.0f / (float)n;
        #pragma unroll
        for (int t = 0; t < 16; ++t) {
            float4 o4 = make_float4(
                rrow[4*t+0] * invn + ((4*t+0 == i) ? 1.f : 0.f),
                rrow[4*t+1] * invn + ((4*t+1 == i) ? 1.f : 0.f),
                rrow[4*t+2] * invn + ((4*t+2 == i) ? 1.f : 0.f),
                rrow[4*t+3] * invn + ((4*t+3 == i) ? 1.f : 0.f));
            *(float4*)&Q[i * DQ + 4 * t] = o4;
        }
        __syncthreads();
    }

    // repeated squaring
    for (int t2 = 0; t2 < ksc; ++t2) {
        #pragma unroll
        for (int t = 0; t < 16; ++t) {
            float4 v = *(const float4*)&Q[i * DQ + 4 * t];
            brow[4*t+0] = v.x; brow[4*t+1] = v.y; brow[4*t+2] = v.z; brow[4*t+3] = v.w;
        }
        #pragma unroll
        for (int j = 0; j < D; ++j) rrow[j] = 0.0f;
        for (int k = 0; k < D; ++k) {
            float bv = brow[k];
            #pragma unroll
            for (int t = 0; t < 16; ++t) {
                float4 q = *(const float4*)&Q[k * DQ + 4 * t];
                rrow[4*t+0] = fmaf(bv, q.x, rrow[4*t+0]);
                rrow[4*t+1] = fmaf(bv, q.y, rrow[4*t+1]);
                rrow[4*t+2] = fmaf(bv, q.z, rrow[4*t+2]);
                rrow[4*t+3] = fmaf(bv, q.w, rrow[4*t+3]);
            }
        }
        __syncthreads();
        #pragma unroll
        for (int t = 0; t < 16; ++t)
            *(float4*)&Q[i * DQ + 4 * t] =
                make_float4(rrow[4*t+0], rrow[4*t+1], rrow[4*t+2], rrow[4*t+3]);
        __syncthreads();
    }

    float* om = out + (size_t)m * DD + i * D;
    #pragma unroll
    for (int t = 0; t < 16; ++t) {
        float4 v = *(const float4*)&Q[i * DQ + 4 * t];
        *(float4*)&om[4 * t] = v;
    }
}

// ========================================================================
extern "C" void kernel_launch(void* const* d_in, const int* in_sizes, int n_in,
                              void* d_out, int out_size) {
    const float* X  = (const float*)d_in[0];
    const float* bw = (const float*)d_in[1];
    float* out = (float*)d_out;

    onesided_log_kernel<<<NMAT, 32>>>(X);
    gram_kernel<<<dim3(4, 4, 8), 256>>>();
    w_kernel<<<NMAT, 256>>>(bw);
    colsum_kernel<<<8, 256>>>();
    ms_kernel<<<dim3(64, 4), 256>>>();
    expm_kernel<<<NMAT, 64>>>(out);
}

// round 11
// speedup vs baseline: 1.5843x; 1.4889x over previous
#include <cuda_runtime.h>
#include <math.h>

#define NMAT 256
#define D 64
#define DD 4096          // 64*64
#define DQ 68            // padded row stride (float4-aligned)
#define NSWEEP_OS 7      // one-sided Jacobi sweeps (6 fails @1.9e-3, 8 proven 1.3e-5)

// ---------------- device scratch (no allocations allowed) ----------------
__device__ float g_L[NMAT * DD];          // log(X) matrices        (4 MB)
__device__ float g_S[NMAT * DD];          // log(X) + M             (4 MB)
__device__ float g_gp[8 * NMAT * NMAT];   // split-K gram partials  (2 MB)
__device__ float g_W[NMAT * NMAT];        // kernel weights         (256 KB)
__device__ float g_sq[NMAT];
__device__ float g_s[NMAT];
__device__ float g_rs[NMAT];              // row sums
__device__ float g_cs[NMAT];              // col sums

// ========================================================================
// Kernel 1: one-sided Jacobi log, one WARP per matrix, columns in registers.
//   Tangent-form rotations with reciprocal-scale tracking (division-free,
//   branch-free round body). True squared norms tracked via exact rotation
//   identities; final norms recomputed exactly. At convergence true columns
//   are lambda_i*v_i: log X = sum_i (log l_i / l_i^2) g_i g_i^T.
// ========================================================================
__global__ __launch_bounds__(32) void onesided_log_kernel(const float* __restrict__ X) {
    __shared__ float Gsm[D * DQ];   // columns (Gsm[r*DQ + col])
    __shared__ float Hsm[D * DQ];   // w_col * column

    const int m    = blockIdx.x;
    const int lane = threadIdx.x;
    const unsigned FULL = 0xffffffffu;
    const float* Xm = X + (size_t)m * DD;

    float a[D], b[D];

    // X is symmetric: column j == row j -> float4 row loads
    {
        const float4* ra = (const float4*)(Xm + (2 * lane)     * D);
        const float4* rb = (const float4*)(Xm + (2 * lane + 1) * D);
        #pragma unroll
        for (int t = 0; t < 16; ++t) {
            float4 v = ra[t];
            a[4*t+0] = v.x; a[4*t+1] = v.y; a[4*t+2] = v.z; a[4*t+3] = v.w;
            float4 w = rb[t];
            b[4*t+0] = w.x; b[4*t+1] = w.y; b[4*t+2] = w.z; b[4*t+3] = w.w;
        }
    }

    // true squared norms + scales and reciprocal scales
    float na, nb, sa = 1.0f, sb = 1.0f, isa = 1.0f, isb = 1.0f;
    {
        float n0 = 0.f, n1 = 0.f, m0 = 0.f, m1 = 0.f;
        #pragma unroll
        for (int k = 0; k < D; k += 2) {
            n0 = fmaf(a[k], a[k], n0);     n1 = fmaf(a[k+1], a[k+1], n1);
            m0 = fmaf(b[k], b[k], m0);     m1 = fmaf(b[k+1], b[k+1], m1);
        }
        na = n0 + n1; nb = m0 + m1;
    }

    for (int sw = 0; sw < NSWEEP_OS; ++sw) {
        for (int rr = 0; rr < 63; ++rr) {
            // unnormalized cross dot (4-way ILP)
            float g0 = 0.f, g1 = 0.f, g2 = 0.f, g3 = 0.f;
            #pragma unroll
            for (int k = 0; k < D; k += 4) {
                g0 = fmaf(a[k+0], b[k+0], g0);
                g1 = fmaf(a[k+1], b[k+1], g1);
                g2 = fmaf(a[k+2], b[k+2], g2);
                g3 = fmaf(a[k+3], b[k+3], g3);
            }
            float ghat = (g0 + g1) + (g2 + g3);
            float gam  = sa * sb * ghat;          // true gamma

            // branch-free rotation params (gam==0 -> t ~ 5e-19 -> no-op)
            float tau = (nb - na) * __fdividef(0.5f, gam);
            tau = fminf(fmaxf(tau, -1e18f), 1e18f);   // NaN-safe clamp
            float opt2 = fmaf(tau, tau, 1.0f);
            float sq   = opt2 * rsqrtf(opt2);         // sqrt(1+tau^2)
            float tt   = copysignf(__fdividef(1.0f, fabsf(tau) + sq), tau);
            float c2   = fmaf(tt, tt, 1.0f);
            float c    = rsqrtf(c2);
            float ic   = c2 * c;                      // exactly 1/c
            float s    = tt * c;

            float u = tt * sb * isa;              // a' = a - u*b (unnormalized)
            float v = tt * sa * isb;              // b' = b + v*a

            #pragma unroll
            for (int k = 0; k < D; ++k) {
                float av = a[k], bv = b[k];
                a[k] = fmaf(-u, bv, av);
                b[k] = fmaf( v, av, bv);
            }
            sa *= c; sb *= c; isa *= ic; isb *= ic;

            // true-norm tracking (exact rotation identities)
            float csg = 2.0f * c * s * gam;
            float cc2 = c * c, ss2 = s * s;
            float na_n = cc2 * na + ss2 * nb - csg;
            float nb_n = ss2 * na + cc2 * nb + csg;
            na = na_n; nb = nb_n;

            // Brent-Luk permutation:
            //  a0 fixed; a1<-b0; a_i<-a_{i-1}; b_i<-b_{i+1}; b31<-a31
            {
                float tn, up, dn, o;
                o = na; tn = (lane == 0) ? nb : na;
                up = __shfl_up_sync(FULL, tn, 1);
                dn = __shfl_down_sync(FULL, nb, 1);
                na = (lane == 0)  ? o : up;
                nb = (lane == 31) ? o : dn;

                o = sa; tn = (lane == 0) ? sb : sa;
                up = __shfl_up_sync(FULL, tn, 1);
                dn = __shfl_down_sync(FULL, sb, 1);
                sa = (lane == 0)  ? o : up;
                sb = (lane == 31) ? o : dn;

                o = isa; tn = (lane == 0) ? isb : isa;
                up = __shfl_up_sync(FULL, tn, 1);
                dn = __shfl_down_sync(FULL, isb, 1);
                isa = (lane == 0)  ? o : up;
                isb = (lane == 31) ? o : dn;
            }
            #pragma unroll
            for (int k = 0; k < D; ++k) {
                float oa  = a[k];
                float tmp = (lane == 0) ? b[k] : oa;
                float up  = __shfl_up_sync(FULL, tmp, 1);
                float dn  = __shfl_down_sync(FULL, b[k], 1);
                a[k] = (lane == 0)  ? oa : up;
                b[k] = (lane == 31) ? oa : dn;
            }
        }

        // per-sweep renormalization (prevents scale drift / overflow)
        #pragma unroll
        for (int k = 0; k < D; ++k) { a[k] *= sa; b[k] *= sb; }
        sa = 1.0f; sb = 1.0f; isa = 1.0f; isb = 1.0f;
    }

    // exact final norms
    {
        float n0 = 0.f, n1 = 0.f, m0 = 0.f, m1 = 0.f;
        #pragma unroll
        for (int k = 0; k < D; k += 2) {
            n0 = fmaf(a[k], a[k], n0);     n1 = fmaf(a[k+1], a[k+1], n1);
            m0 = fmaf(b[k], b[k], m0);     m1 = fmaf(b[k+1], b[k+1], m1);
        }
        na = n0 + n1; nb = m0 + m1;
    }
    // weight = log(lambda)/lambda^2, lambda^2 = |g|^2
    float wa = 0.5f * logf(fmaxf(na, 1e-30f)) / na;
    float wb = 0.5f * logf(fmaxf(nb, 1e-30f)) / nb;

    // stash columns + scaled columns to smem
    {
        const int ia = 2 * lane, ib = 2 * lane + 1;
        #pragma unroll
        for (int r = 0; r < D; ++r) {
            Gsm[r * DQ + ia] = a[r];
            Hsm[r * DQ + ia] = wa * a[r];
            Gsm[r * DQ + ib] = b[r];
            Hsm[r * DQ + ib] = wb * b[r];
        }
    }
    __syncwarp();

    // L[r,c] = sum_i H[r,i] * G[c,i]; each lane computes rows 2*lane, 2*lane+1
    const int r0 = 2 * lane, r1 = 2 * lane + 1;
    #pragma unroll
    for (int t = 0; t < 16; ++t) {
        float4 h0 = *(const float4*)&Hsm[r0 * DQ + 4 * t];
        a[4*t+0] = h0.x; a[4*t+1] = h0.y; a[4*t+2] = h0.z; a[4*t+3] = h0.w;
        float4 h1 = *(const float4*)&Hsm[r1 * DQ + 4 * t];
        b[4*t+0] = h1.x; b[4*t+1] = h1.y; b[4*t+2] = h1.z; b[4*t+3] = h1.w;
    }

    float ssum = 0.f, sqsum = 0.f;
    float* o0 = g_L + (size_t)m * DD + r0 * D;
    float* o1 = g_L + (size_t)m * DD + r1 * D;
    for (int c4 = 0; c4 < D; c4 += 4) {
        float acc0[4] = {0.f, 0.f, 0.f, 0.f};
        float acc1[4] = {0.f, 0.f, 0.f, 0.f};
        #pragma unroll
        for (int cc = 0; cc < 4; ++cc) {
            const int c = c4 + cc;
            #pragma unroll
            for (int t = 0; t < 16; ++t) {
                float4 g = *(const float4*)&Gsm[c * DQ + 4 * t];  // broadcast
                acc0[cc] = fmaf(a[4*t+0], g.x, acc0[cc]);
                acc0[cc] = fmaf(a[4*t+1], g.y, acc0[cc]);
                acc0[cc] = fmaf(a[4*t+2], g.z, acc0[cc]);
                acc0[cc] = fmaf(a[4*t+3], g.w, acc0[cc]);
                acc1[cc] = fmaf(b[4*t+0], g.x, acc1[cc]);
                acc1[cc] = fmaf(b[4*t+1], g.y, acc1[cc]);
                acc1[cc] = fmaf(b[4*t+2], g.z, acc1[cc]);
                acc1[cc] = fmaf(b[4*t+3], g.w, acc1[cc]);
            }
        }
        *(float4*)&o0[c4] = make_float4(acc0[0], acc0[1], acc0[2], acc0[3]);
        *(float4*)&o1[c4] = make_float4(acc1[0], acc1[1], acc1[2], acc1[3]);
        #pragma unroll
        for (int cc = 0; cc < 4; ++cc) {
            ssum += acc0[cc] + acc1[cc];
            sqsum = fmaf(acc0[cc], acc0[cc], sqsum);
            sqsum = fmaf(acc1[cc], acc1[cc], sqsum);
        }
    }
    // warp reduce s / sq
    #pragma unroll
    for (int o = 16; o; o >>= 1) {
        ssum  += __shfl_down_sync(FULL, ssum,  o);
        sqsum += __shfl_down_sync(FULL, sqsum, o);
    }
    if (lane == 0) { g_s[m] = ssum; g_sq[m] = sqsum; }
}

// ========================================================================
// Kernel 2: gram partials  g_gp[z][i][j] = sum_{k in z-chunk} L[i][k] L[j][k]
// ========================================================================
__global__ __launch_bounds__(256) void gram_kernel() {
    __shared__ float As[64 * 17];
    __shared__ float Bs[64 * 17];
    const int bj = blockIdx.x, bi = blockIdx.y, bz = blockIdx.z;
    const int tid = threadIdx.x;
    const int ty = tid >> 4, tx = tid & 15;

    float acc[4][4];
    #pragma unroll
    for (int r = 0; r < 4; ++r)
        #pragma unroll
        for (int c = 0; c < 4; ++c) acc[r][c] = 0.0f;

    const int k0 = bz * 512;
    for (int kc = 0; kc < 512; kc += 16) {
        for (int l = tid; l < 1024; l += 256) {
            int r = l >> 4, kk = l & 15;
            As[r * 17 + kk] = g_L[(size_t)(bi * 64 + r) * DD + k0 + kc + kk];
            Bs[r * 17 + kk] = g_L[(size_t)(bj * 64 + r) * DD + k0 + kc + kk];
        }
        __syncthreads();
        #pragma unroll
        for (int kk = 0; kk < 16; ++kk) {
            float a[4], b[4];
            #pragma unroll
            for (int r = 0; r < 4; ++r) a[r] = As[(ty * 4 + r) * 17 + kk];
            #pragma unroll
            for (int c = 0; c < 4; ++c) b[c] = Bs[(tx * 4 + c) * 17 + kk];
            #pragma unroll
            for (int r = 0; r < 4; ++r)
                #pragma unroll
                for (int c = 0; c < 4; ++c)
                    acc[r][c] = fmaf(a[r], b[c], acc[r][c]);
        }
        __syncthreads();
    }
    #pragma unroll
    for (int r = 0; r < 4; ++r)
        #pragma unroll
        for (int c = 0; c < 4; ++c)
            g_gp[((size_t)bz * NMAT + bi * 64 + ty * 4 + r) * NMAT + bj * 64 + tx * 4 + c] = acc[r][c];
}

// ========================================================================
// Kernel 3: W = exp(-0.5 * pds / bw^2), fused row sums.  block = row i
// ========================================================================
__global__ __launch_bounds__(256) void w_kernel(const float* __restrict__ bwp) {
    __shared__ float red[8];
    const int i = blockIdx.x;
    const int j = threadIdx.x;

    float g = 0.0f;
    #pragma unroll
    for (int z = 0; z < 8; ++z)
        g += g_gp[((size_t)z * NMAT + i) * NMAT + j];

    const float bw  = bwp[0];
    const float inv = 0.5f / (bw * bw);
    const float eps = 1e-7f;
    float pds = g_sq[i] + g_sq[j] - 2.0f * g
              + 2.0f * eps * (g_s[j] - g_s[i])
              + eps * eps * 4096.0f;
    float wv = expf(-pds * inv);
    g_W[i * NMAT + j] = wv;

    float sum = wv;
    #pragma unroll
    for (int o = 16; o; o >>= 1) sum += __shfl_down_sync(0xffffffffu, sum, o);
    if ((j & 31) == 0) red[j >> 5] = sum;
    __syncthreads();
    if (j == 0) {
        float t = 0.0f;
        #pragma unroll
        for (int w = 0; w < 8; ++w) t += red[w];
        g_rs[i] = t;
    }
}

// col sums: 8 blocks x 256 threads, coalesced
__global__ __launch_bounds__(256) void colsum_kernel() {
    __shared__ float part[8][32];
    const int c0 = blockIdx.x * 32;
    const int c = threadIdx.x & 31;
    const int rchunk = threadIdx.x >> 5;
    float s = 0.0f;
    #pragma unroll
    for (int rr = 0; rr < 32; ++rr)
        s += g_W[(rchunk * 32 + rr) * NMAT + c0 + c];
    part[rchunk][c] = s;
    __syncthreads();
    if (threadIdx.x < 32) {
        float t = 0.0f;
        #pragma unroll
        for (int w = 0; w < 8; ++w) t += part[w][threadIdx.x];
        g_cs[c0 + threadIdx.x] = t;
    }
}

// ========================================================================
// Kernel 4: C = W^T L, fused mean-shift epilogue -> S = L_k + (C - cs_k L_k)/rs_k
// ========================================================================
__global__ __launch_bounds__(256) void ms_kernel() {
    __shared__ float Wt[16 * 65];
    __shared__ float Lt[16 * 65];
    const int bc = blockIdx.x;   // column tile
    const int bk = blockIdx.y;   // k (output row) tile
    const int tid = threadIdx.x;
    const int ty = tid >> 4, tx = tid & 15;

    float acc[4][4];
    #pragma unroll
    for (int r = 0; r < 4; ++r)
        #pragma unroll
        for (int c = 0; c < 4; ++c) acc[r][c] = 0.0f;

    for (int j0 = 0; j0 < NMAT; j0 += 16) {
        for (int l = tid; l < 1024; l += 256) {
            int jj = l >> 6, c = l & 63;
            Wt[jj * 65 + c] = g_W[(j0 + jj) * NMAT + bk * 64 + c];
            Lt[jj * 65 + c] = g_L[(size_t)(j0 + jj) * DD + bc * 64 + c];
        }
        __syncthreads();
        #pragma unroll
        for (int jj = 0; jj < 16; ++jj) {
            float a[4], b[4];
            #pragma unroll
            for (int r = 0; r < 4; ++r) a[r] = Wt[jj * 65 + ty * 4 + r];
            #pragma unroll
            for (int c = 0; c < 4; ++c) b[c] = Lt[jj * 65 + tx * 4 + c];
            #pragma unroll
            for (int r = 0; r < 4; ++r)
                #pragma unroll
                for (int c = 0; c < 4; ++c)
                    acc[r][c] = fmaf(a[r], b[c], acc[r][c]);
        }
        __syncthreads();
    }
    #pragma unroll
    for (int r = 0; r < 4; ++r) {
        int k = bk * 64 + ty * 4 + r;
        float rs = g_rs[k], cs = g_cs[k];
        float inv_rs = 1.0f / rs;
        #pragma unroll
        for (int c = 0; c < 4; ++c) {
            int col = bc * 64 + tx * 4 + c;
            float lk = g_L[(size_t)k * DD + col];
            g_S[(size_t)k * DD + col] = lk + (acc[r][c] - cs * lk) * inv_rs;
        }
    }
}

// ========================================================================
// Kernel 5: expm(S), scaling-and-squaring + order-8 Horner (first step folded
//   into init). B row loaded straight from gmem; no smem staging pass.
// ========================================================================
__global__ __launch_bounds__(64) void expm_kernel(float* __restrict__ out) {
    __shared__ float Q[D * DQ];
    __shared__ float redw[2];

    const int m = blockIdx.x;
    const int i = threadIdx.x;

    // own B row straight from gmem
    float brow[D];
    {
        const float4* sr = (const float4*)(g_S + (size_t)m * DD + i * D);
        #pragma unroll
        for (int t = 0; t < 16; ++t) {
            float4 v = sr[t];
            brow[4*t+0] = v.x; brow[4*t+1] = v.y;
            brow[4*t+2] = v.z; brow[4*t+3] = v.w;
        }
    }

    // Frobenius norm via block reduction (2 warps)
    float local = 0.0f;
    #pragma unroll
    for (int k = 0; k < D; ++k) local = fmaf(brow[k], brow[k], local);
    #pragma unroll
    for (int o = 16; o; o >>= 1) local += __shfl_down_sync(0xffffffffu, local, o);
    if ((i & 31) == 0) redw[i >> 5] = local;
    __syncthreads();

    float nf = sqrtf(redw[0] + redw[1]);
    int ksc = 0;
    if (nf > 0.5f) {
        ksc = (int)ceilf(log2f(nf * 2.0f));
        if (ksc > 15) ksc = 15;
        if (ksc < 0)  ksc = 0;
    }
    const float sc = exp2f((float)(-ksc));
    #pragma unroll
    for (int k = 0; k < D; ++k) brow[k] *= sc;

    // init Q = I + B/8  (folds first Horner step, order 8 total)
    {
        const float i8 = 1.0f / 8.0f;
        #pragma unroll
        for (int t = 0; t < 16; ++t) {
            float4 o4 = make_float4(
                brow[4*t+0] * i8 + ((4*t+0 == i) ? 1.f : 0.f),
                brow[4*t+1] * i8 + ((4*t+1 == i) ? 1.f : 0.f),
                brow[4*t+2] * i8 + ((4*t+2 == i) ? 1.f : 0.f),
                brow[4*t+3] * i8 + ((4*t+3 == i) ? 1.f : 0.f));
            *(float4*)&Q[i * DQ + 4 * t] = o4;
        }
    }
    __syncthreads();

    float rrow[D];

    // Horner: Q_{n-1} = I + (B * Q_n)/n, n = 7..1
    for (int n = 7; n >= 1; --n) {
        #pragma unroll
        for (int j = 0; j < D; ++j) rrow[j] = 0.0f;
        for (int k = 0; k < D; ++k) {
            float bv = brow[k];
            #pragma unroll
            for (int t = 0; t < 16; ++t) {
                float4 q = *(const float4*)&Q[k * DQ + 4 * t];  // broadcast
                rrow[4*t+0] = fmaf(bv, q.x, rrow[4*t+0]);
                rrow[4*t+1] = fmaf(bv, q.y, rrow[4*t+1]);
                rrow[4*t+2] = fmaf(bv, q.z, rrow[4*t+2]);
                rrow[4*t+3] = fmaf(bv, q.w, rrow[4*t+3]);
            }
        }
        __syncthreads();
        const float invn = 1.0f / (float)n;
        #pragma unroll
        for (int t = 0; t < 16; ++t) {
            float4 o4 = make_float4(
                rrow[4*t+0] * invn + ((4*t+0 == i) ? 1.f : 0.f),
                rrow[4*t+1] * invn + ((4*t+1 == i) ? 1.f : 0.f),
                rrow[4*t+2] * invn + ((4*t+2 == i) ? 1.f : 0.f),
                rrow[4*t+3] * invn + ((4*t+3 == i) ? 1.f : 0.f));
            *(float4*)&Q[i * DQ + 4 * t] = o4;
        }
        __syncthreads();
    }

    // repeated squaring
    for (int t2 = 0; t2 < ksc; ++t2) {
        #pragma unroll
        for (int t = 0; t < 16; ++t) {
            float4 v = *(const float4*)&Q[i * DQ + 4 * t];
            brow[4*t+0] = v.x; brow[4*t+1] = v.y; brow[4*t+2] = v.z; brow[4*t+3] = v.w;
        }
        #pragma unroll
        for (int j = 0; j < D; ++j) rrow[j] = 0.0f;
        for (int k = 0; k < D; ++k) {
            float bv = brow[k];
            #pragma unroll
            for (int t = 0; t < 16; ++t) {
                float4 q = *(const float4*)&Q[k * DQ + 4 * t];
                rrow[4*t+0] = fmaf(bv, q.x, rrow[4*t+0]);
                rrow[4*t+1] = fmaf(bv, q.y, rrow[4*t+1]);
                rrow[4*t+2] = fmaf(bv, q.z, rrow[4*t+2]);
                rrow[4*t+3] = fmaf(bv, q.w, rrow[4*t+3]);
            }
        }
        __syncthreads();
        #pragma unroll
        for (int t = 0; t < 16; ++t)
            *(float4*)&Q[i * DQ + 4 * t] =
                make_float4(rrow[4*t+0], rrow[4*t+1], rrow[4*t+2], rrow[4*t+3]);
        __syncthreads();
    }

    float* om = out + (size_t)m * DD + i * D;
    #pragma unroll
    for (int t = 0; t < 16; ++t) {
        float4 v = *(const float4*)&Q[i * DQ + 4 * t];
        *(float4*)&om[4 * t] = v;
    }
}

// ========================================================================
extern "C" void kernel_launch(void* const* d_in, const int* in_sizes, int n_in,
                              void* d_out, int out_size) {
    const float* X  = (const float*)d_in[0];
    const float* bw = (const float*)d_in[1];
    float* out = (float*)d_out;

    onesided_log_kernel<<<NMAT, 32>>>(X);
    gram_kernel<<<dim3(4, 4, 8), 256>>>();
    w_kernel<<<NMAT, 256>>>(bw);
    colsum_kernel<<<8, 256>>>();
    ms_kernel<<<dim3(64, 4), 256>>>();
    expm_kernel<<<NMAT, 64>>>(out);
}

// round 12
// speedup vs baseline: 1.8252x; 1.1520x over previous
#include <cuda_runtime.h>
#include <math.h>

#define NMAT 256
#define D 64
#define DD 4096          // 64*64
#define DQ 68            // padded row stride (float4-aligned)
#define NSWEEP_OS 7      // one-sided Jacobi sweeps (6 fails @1.9e-3, 8 proven 1.3e-5)

// ---------------- device scratch (no allocations allowed) ----------------
__device__ float g_L[NMAT * DD];          // log(X) matrices        (4 MB)
__device__ float g_S[NMAT * DD];          // log(X) + M             (4 MB)
__device__ float g_gp[8 * NMAT * NMAT];   // split-K gram partials  (2 MB)
__device__ float g_W[NMAT * NMAT];        // kernel weights         (256 KB)
__device__ float g_sq[NMAT];
__device__ float g_s[NMAT];
__device__ float g_rs[NMAT];              // row sums
__device__ float g_cs[NMAT];              // col sums

// ========================================================================
// Kernel 1: one-sided Jacobi log, TWO warps per matrix (64-thread CTA).
//   Lane l of warp w holds elements [32w, 32w+32) of column pair (2l, 2l+1).
//   Tangent-form rotations, division/branch-free chain. Full cross-dot via
//   one double-buffered smem exchange + __syncthreads per round; both warps
//   compute bit-identical scalars (commutative partial sums). Brent-Luk
//   permutation runs within each warp (same lane pattern -> halves of a
//   column move together). At convergence true columns are lambda_i*v_i:
//   log X = sum_i (log l_i / l_i^2) g_i g_i^T.
// ========================================================================
__global__ __launch_bounds__(64) void onesided_log_kernel(const float* __restrict__ X) {
    __shared__ float Gsm[D * DQ];          // Gsm[element*DQ + column]
    __shared__ float Hsm[D * DQ];          // w_col * column
    __shared__ float pdot[2][2][32];       // [buf][warp][lane] partial cross-dots
    __shared__ float2 pnorm[2][32];        // [warp][lane] partial norms (init/final)
    __shared__ float reds[2], redq[2];

    const int m    = blockIdx.x;
    const int tid  = threadIdx.x;
    const int w    = tid >> 5;
    const int ow   = w ^ 1;
    const int lane = tid & 31;
    const unsigned FULL = 0xffffffffu;
    const float* Xm = X + (size_t)m * DD;

    float a[32], b[32];

    // X symmetric: column c == row c. Each warp loads its element half.
    {
        const float4* ra = (const float4*)(Xm + (2 * lane)     * D + 32 * w);
        const float4* rb = (const float4*)(Xm + (2 * lane + 1) * D + 32 * w);
        #pragma unroll
        for (int t = 0; t < 8; ++t) {
            float4 v = ra[t];
            a[4*t+0] = v.x; a[4*t+1] = v.y; a[4*t+2] = v.z; a[4*t+3] = v.w;
            float4 u = rb[t];
            b[4*t+0] = u.x; b[4*t+1] = u.y; b[4*t+2] = u.z; b[4*t+3] = u.w;
        }
    }

    // initial full norms via partial exchange
    float na, nb, sa = 1.0f, sb = 1.0f, isa = 1.0f, isb = 1.0f;
    {
        float n0 = 0.f, n1 = 0.f, m0 = 0.f, m1 = 0.f;
        #pragma unroll
        for (int k = 0; k < 32; k += 2) {
            n0 = fmaf(a[k], a[k], n0);     n1 = fmaf(a[k+1], a[k+1], n1);
            m0 = fmaf(b[k], b[k], m0);     m1 = fmaf(b[k+1], b[k+1], m1);
        }
        float pa = n0 + n1, pb2 = m0 + m1;
        pnorm[w][lane] = make_float2(pa, pb2);
        __syncthreads();
        float2 o = pnorm[ow][lane];
        na = pa + o.x;            // commutative -> identical in both warps
        nb = pb2 + o.y;
    }

    int pb = 0;
    for (int sw = 0; sw < NSWEEP_OS; ++sw) {
        for (int rr = 0; rr < 63; ++rr) {
            // partial cross dot (2-way ILP)
            float g0 = 0.f, g1 = 0.f;
            #pragma unroll
            for (int k = 0; k < 32; k += 2) {
                g0 = fmaf(a[k+0], b[k+0], g0);
                g1 = fmaf(a[k+1], b[k+1], g1);
            }
            float gp = g0 + g1;
            pdot[pb][w][lane] = gp;
            __syncthreads();
            float ghat = gp + pdot[pb][ow][lane];   // commutative sum
            pb ^= 1;

            float gam = sa * sb * ghat;             // true gamma

            // branch-free rotation params (gam==0 -> t ~ 5e-19 -> no-op)
            float tau = (nb - na) * __fdividef(0.5f, gam);
            tau = fminf(fmaxf(tau, -1e18f), 1e18f); // NaN-safe clamp
            float opt2 = fmaf(tau, tau, 1.0f);
            float sq   = opt2 * rsqrtf(opt2);       // sqrt(1+tau^2)
            float tt   = copysignf(__fdividef(1.0f, fabsf(tau) + sq), tau);
            float c2   = fmaf(tt, tt, 1.0f);
            float c    = rsqrtf(c2);
            float ic   = c2 * c;                    // exactly 1/c
            float s    = tt * c;

            float u = tt * sb * isa;                // a' = a - u*b
            float v = tt * sa * isb;                // b' = b + v*a

            #pragma unroll
            for (int k = 0; k < 32; ++k) {
                float av = a[k], bv = b[k];
                a[k] = fmaf(-u, bv, av);
                b[k] = fmaf( v, av, bv);
            }
            sa *= c; sb *= c; isa *= ic; isb *= ic;

            // true-norm tracking (exact rotation identities)
            float csg = 2.0f * c * s * gam;
            float cc2 = c * c, ss2 = s * s;
            float na_n = cc2 * na + ss2 * nb - csg;
            float nb_n = ss2 * na + cc2 * nb + csg;
            na = na_n; nb = nb_n;

            // Brent-Luk permutation (within each warp; identical patterns)
            {
                float tn, up, dn, o;
                o = na; tn = (lane == 0) ? nb : na;
                up = __shfl_up_sync(FULL, tn, 1);
                dn = __shfl_down_sync(FULL, nb, 1);
                na = (lane == 0)  ? o : up;
                nb = (lane == 31) ? o : dn;

                o = sa; tn = (lane == 0) ? sb : sa;
                up = __shfl_up_sync(FULL, tn, 1);
                dn = __shfl_down_sync(FULL, sb, 1);
                sa = (lane == 0)  ? o : up;
                sb = (lane == 31) ? o : dn;

                o = isa; tn = (lane == 0) ? isb : isa;
                up = __shfl_up_sync(FULL, tn, 1);
                dn = __shfl_down_sync(FULL, isb, 1);
                isa = (lane == 0)  ? o : up;
                isb = (lane == 31) ? o : dn;
            }
            #pragma unroll
            for (int k = 0; k < 32; ++k) {
                float oa  = a[k];
                float tmp = (lane == 0) ? b[k] : oa;
                float up  = __shfl_up_sync(FULL, tmp, 1);
                float dn  = __shfl_down_sync(FULL, b[k], 1);
                a[k] = (lane == 0)  ? oa : up;
                b[k] = (lane == 31) ? oa : dn;
            }
        }

        // per-sweep renormalization (scales replicated across warps)
        #pragma unroll
        for (int k = 0; k < 32; ++k) { a[k] *= sa; b[k] *= sb; }
        sa = 1.0f; sb = 1.0f; isa = 1.0f; isb = 1.0f;
    }

    // exact final norms via partial exchange
    {
        float n0 = 0.f, n1 = 0.f, m0 = 0.f, m1 = 0.f;
        #pragma unroll
        for (int k = 0; k < 32; k += 2) {
            n0 = fmaf(a[k], a[k], n0);     n1 = fmaf(a[k+1], a[k+1], n1);
            m0 = fmaf(b[k], b[k], m0);     m1 = fmaf(b[k+1], b[k+1], m1);
        }
        float pa = n0 + n1, pb2 = m0 + m1;
        pnorm[w][lane] = make_float2(pa, pb2);
        __syncthreads();
        float2 o = pnorm[ow][lane];
        na = pa + o.x; nb = pb2 + o.y;
    }

    // weight = log(lambda)/lambda^2 with lambda^2 = |g|^2
    float wa = 0.5f * logf(fmaxf(na, 1e-30f)) / na;
    float wb = 0.5f * logf(fmaxf(nb, 1e-30f)) / nb;

    // stash columns + scaled columns (each warp writes its element range)
    {
        const int ia = 2 * lane, ib = 2 * lane + 1;
        #pragma unroll
        for (int k = 0; k < 32; ++k) {
            int r = 32 * w + k;
            Gsm[r * DQ + ia] = a[k];
            Hsm[r * DQ + ia] = wa * a[k];
            Gsm[r * DQ + ib] = b[k];
            Hsm[r * DQ + ib] = wb * b[k];
        }
    }
    __syncthreads();

    // L[r,c] = sum_col Hsm[r,col] * Gsm[c,col]; thread computes row r = tid
    const int r = tid;
    float hrow[64];
    #pragma unroll
    for (int t = 0; t < 16; ++t) {
        float4 h = *(const float4*)&Hsm[r * DQ + 4 * t];
        hrow[4*t+0] = h.x; hrow[4*t+1] = h.y; hrow[4*t+2] = h.z; hrow[4*t+3] = h.w;
    }

    float ssum = 0.f, sqsum = 0.f;
    float* orow = g_L + (size_t)m * DD + r * D;
    for (int c4 = 0; c4 < D; c4 += 4) {
        float acc[4] = {0.f, 0.f, 0.f, 0.f};
        #pragma unroll
        for (int cc = 0; cc < 4; ++cc) {
            const int c = c4 + cc;
            #pragma unroll
            for (int t = 0; t < 16; ++t) {
                float4 g = *(const float4*)&Gsm[c * DQ + 4 * t];  // broadcast
                acc[cc] = fmaf(hrow[4*t+0], g.x, acc[cc]);
                acc[cc] = fmaf(hrow[4*t+1], g.y, acc[cc]);
                acc[cc] = fmaf(hrow[4*t+2], g.z, acc[cc]);
                acc[cc] = fmaf(hrow[4*t+3], g.w, acc[cc]);
            }
        }
        *(float4*)&orow[c4] = make_float4(acc[0], acc[1], acc[2], acc[3]);
        #pragma unroll
        for (int cc = 0; cc < 4; ++cc) {
            ssum += acc[cc];
            sqsum = fmaf(acc[cc], acc[cc], sqsum);
        }
    }
    #pragma unroll
    for (int o = 16; o; o >>= 1) {
        ssum  += __shfl_down_sync(FULL, ssum,  o);
        sqsum += __shfl_down_sync(FULL, sqsum, o);
    }
    if (lane == 0) { reds[w] = ssum; redq[w] = sqsum; }
    __syncthreads();
    if (tid == 0) {
        g_s[m]  = reds[0] + reds[1];
        g_sq[m] = redq[0] + redq[1];
    }
}

// ========================================================================
// Kernel 2: gram partials  g_gp[z][i][j] = sum_{k in z-chunk} L[i][k] L[j][k]
// ========================================================================
__global__ __launch_bounds__(256) void gram_kernel() {
    __shared__ float As[64 * 17];
    __shared__ float Bs[64 * 17];
    const int bj = blockIdx.x, bi = blockIdx.y, bz = blockIdx.z;
    const int tid = threadIdx.x;
    const int ty = tid >> 4, tx = tid & 15;

    float acc[4][4];
    #pragma unroll
    for (int r = 0; r < 4; ++r)
        #pragma unroll
        for (int c = 0; c < 4; ++c) acc[r][c] = 0.0f;

    const int k0 = bz * 512;
    for (int kc = 0; kc < 512; kc += 16) {
        for (int l = tid; l < 1024; l += 256) {
            int r = l >> 4, kk = l & 15;
            As[r * 17 + kk] = g_L[(size_t)(bi * 64 + r) * DD + k0 + kc + kk];
            Bs[r * 17 + kk] = g_L[(size_t)(bj * 64 + r) * DD + k0 + kc + kk];
        }
        __syncthreads();
        #pragma unroll
        for (int kk = 0; kk < 16; ++kk) {
            float a[4], b[4];
            #pragma unroll
            for (int r = 0; r < 4; ++r) a[r] = As[(ty * 4 + r) * 17 + kk];
            #pragma unroll
            for (int c = 0; c < 4; ++c) b[c] = Bs[(tx * 4 + c) * 17 + kk];
            #pragma unroll
            for (int r = 0; r < 4; ++r)
                #pragma unroll
                for (int c = 0; c < 4; ++c)
                    acc[r][c] = fmaf(a[r], b[c], acc[r][c]);
        }
        __syncthreads();
    }
    #pragma unroll
    for (int r = 0; r < 4; ++r)
        #pragma unroll
        for (int c = 0; c < 4; ++c)
            g_gp[((size_t)bz * NMAT + bi * 64 + ty * 4 + r) * NMAT + bj * 64 + tx * 4 + c] = acc[r][c];
}

// ========================================================================
// Kernel 3: W = exp(-0.5 * pds / bw^2), fused row sums.  block = row i
// ========================================================================
__global__ __launch_bounds__(256) void w_kernel(const float* __restrict__ bwp) {
    __shared__ float red[8];
    const int i = blockIdx.x;
    const int j = threadIdx.x;

    float g = 0.0f;
    #pragma unroll
    for (int z = 0; z < 8; ++z)
        g += g_gp[((size_t)z * NMAT + i) * NMAT + j];

    const float bw  = bwp[0];
    const float inv = 0.5f / (bw * bw);
    const float eps = 1e-7f;
    float pds = g_sq[i] + g_sq[j] - 2.0f * g
              + 2.0f * eps * (g_s[j] - g_s[i])
              + eps * eps * 4096.0f;
    float wv = expf(-pds * inv);
    g_W[i * NMAT + j] = wv;

    float sum = wv;
    #pragma unroll
    for (int o = 16; o; o >>= 1) sum += __shfl_down_sync(0xffffffffu, sum, o);
    if ((j & 31) == 0) red[j >> 5] = sum;
    __syncthreads();
    if (j == 0) {
        float t = 0.0f;
        #pragma unroll
        for (int w = 0; w < 8; ++w) t += red[w];
        g_rs[i] = t;
    }
}

// col sums: 8 blocks x 256 threads, coalesced
__global__ __launch_bounds__(256) void colsum_kernel() {
    __shared__ float part[8][32];
    const int c0 = blockIdx.x * 32;
    const int c = threadIdx.x & 31;
    const int rchunk = threadIdx.x >> 5;
    float s = 0.0f;
    #pragma unroll
    for (int rr = 0; rr < 32; ++rr)
        s += g_W[(rchunk * 32 + rr) * NMAT + c0 + c];
    part[rchunk][c] = s;
    __syncthreads();
    if (threadIdx.x < 32) {
        float t = 0.0f;
        #pragma unroll
        for (int w = 0; w < 8; ++w) t += part[w][threadIdx.x];
        g_cs[c0 + threadIdx.x] = t;
    }
}

// ========================================================================
// Kernel 4: C = W^T L, fused mean-shift epilogue -> S = L_k + (C - cs_k L_k)/rs_k
// ========================================================================
__global__ __launch_bounds__(256) void ms_kernel() {
    __shared__ float Wt[16 * 65];
    __shared__ float Lt[16 * 65];
    const int bc = blockIdx.x;   // column tile
    const int bk = blockIdx.y;   // k (output row) tile
    const int tid = threadIdx.x;
    const int ty = tid >> 4, tx = tid & 15;

    float acc[4][4];
    #pragma unroll
    for (int r = 0; r < 4; ++r)
        #pragma unroll
        for (int c = 0; c < 4; ++c) acc[r][c] = 0.0f;

    for (int j0 = 0; j0 < NMAT; j0 += 16) {
        for (int l = tid; l < 1024; l += 256) {
            int jj = l >> 6, c = l & 63;
            Wt[jj * 65 + c] = g_W[(j0 + jj) * NMAT + bk * 64 + c];
            Lt[jj * 65 + c] = g_L[(size_t)(j0 + jj) * DD + bc * 64 + c];
        }
        __syncthreads();
        #pragma unroll
        for (int jj = 0; jj < 16; ++jj) {
            float a[4], b[4];
            #pragma unroll
            for (int r = 0; r < 4; ++r) a[r] = Wt[jj * 65 + ty * 4 + r];
            #pragma unroll
            for (int c = 0; c < 4; ++c) b[c] = Lt[jj * 65 + tx * 4 + c];
            #pragma unroll
            for (int r = 0; r < 4; ++r)
                #pragma unroll
                for (int c = 0; c < 4; ++c)
                    acc[r][c] = fmaf(a[r], b[c], acc[r][c]);
        }
        __syncthreads();
    }
    #pragma unroll
    for (int r = 0; r < 4; ++r) {
        int k = bk * 64 + ty * 4 + r;
        float rs = g_rs[k], cs = g_cs[k];
        float inv_rs = 1.0f / rs;
        #pragma unroll
        for (int c = 0; c < 4; ++c) {
            int col = bc * 64 + tx * 4 + c;
            float lk = g_L[(size_t)k * DD + col];
            g_S[(size_t)k * DD + col] = lk + (acc[r][c] - cs * lk) * inv_rs;
        }
    }
}

// ========================================================================
// Kernel 5: expm(S), scaling-and-squaring + order-8 Horner (first step folded
//   into init). 128 threads: 2 threads per row, each owns a 32-column half.
// ========================================================================
__global__ __launch_bounds__(128) void expm_kernel(float* __restrict__ out) {
    __shared__ float Q[D * DQ];
    __shared__ float redw[4];

    const int m   = blockIdx.x;
    const int tid = threadIdx.x;
    const int i   = tid >> 1;          // row
    const int c0  = (tid & 1) * 32;    // column half base

    // full B row straight from gmem (both half-threads load the same row)
    float brow[64];
    {
        const float4* sr = (const float4*)(g_S + (size_t)m * DD + i * D);
        #pragma unroll
        for (int t = 0; t < 16; ++t) {
            float4 v = sr[t];
            brow[4*t+0] = v.x; brow[4*t+1] = v.y;
            brow[4*t+2] = v.z; brow[4*t+3] = v.w;
        }
    }

    // Frobenius norm: each thread contributes its own half's squares (exact cover)
    float local = 0.0f;
    #pragma unroll
    for (int k = 0; k < 32; ++k) local = fmaf(brow[c0 + k], brow[c0 + k], local);
    #pragma unroll
    for (int o = 16; o; o >>= 1) local += __shfl_down_sync(0xffffffffu, local, o);
    if ((tid & 31) == 0) redw[tid >> 5] = local;
    __syncthreads();

    float nf = sqrtf((redw[0] + redw[1]) + (redw[2] + redw[3]));
    int ksc = 0;
    if (nf > 0.5f) {
        ksc = (int)ceilf(log2f(nf * 2.0f));
        if (ksc > 15) ksc = 15;
        if (ksc < 0)  ksc = 0;
    }
    const float sc = exp2f((float)(-ksc));
    #pragma unroll
    for (int k = 0; k < 64; ++k) brow[k] *= sc;

    // init Q = I + B/8 (folds first Horner step; order 8 total)
    {
        const float i8 = 1.0f / 8.0f;
        #pragma unroll
        for (int t = 0; t < 8; ++t) {
            int c = c0 + 4 * t;
            float4 o4 = make_float4(
                brow[c+0] * i8 + ((c+0 == i) ? 1.f : 0.f),
                brow[c+1] * i8 + ((c+1 == i) ? 1.f : 0.f),
                brow[c+2] * i8 + ((c+2 == i) ? 1.f : 0.f),
                brow[c+3] * i8 + ((c+3 == i) ? 1.f : 0.f));
            *(float4*)&Q[i * DQ + c] = o4;
        }
    }
    __syncthreads();

    float rrow[32];

    // Horner: Q_{n-1} = I + (B * Q_n)/n, n = 7..1
    for (int n = 7; n >= 1; --n) {
        #pragma unroll
        for (int j = 0; j < 32; ++j) rrow[j] = 0.0f;
        for (int k = 0; k < D; ++k) {
            float bv = brow[k];
            #pragma unroll
            for (int t = 0; t < 8; ++t) {
                float4 q = *(const float4*)&Q[k * DQ + c0 + 4 * t];
                rrow[4*t+0] = fmaf(bv, q.x, rrow[4*t+0]);
                rrow[4*t+1] = fmaf(bv, q.y, rrow[4*t+1]);
                rrow[4*t+2] = fmaf(bv, q.z, rrow[4*t+2]);
                rrow[4*t+3] = fmaf(bv, q.w, rrow[4*t+3]);
            }
        }
        __syncthreads();
        const float invn = 1.0f / (float)n;
        #pragma unroll
        for (int t = 0; t < 8; ++t) {
            int c = c0 + 4 * t;
            float4 o4 = make_float4(
                rrow[4*t+0] * invn + ((c+0 == i) ? 1.f : 0.f),
                rrow[4*t+1] * invn + ((c+1 == i) ? 1.f : 0.f),
                rrow[4*t+2] * invn + ((c+2 == i) ? 1.f : 0.f),
                rrow[4*t+3] * invn + ((c+3 == i) ? 1.f : 0.f));
            *(float4*)&Q[i * DQ + c] = o4;
        }
        __syncthreads();
    }

    // repeated squaring (ksc uniform across the block)
    for (int t2 = 0; t2 < ksc; ++t2) {
        #pragma unroll
        for (int t = 0; t < 16; ++t) {
            float4 v = *(const float4*)&Q[i * DQ + 4 * t];
            brow[4*t+0] = v.x; brow[4*t+1] = v.y; brow[4*t+2] = v.z; brow[4*t+3] = v.w;
        }
        #pragma unroll
        for (int j = 0; j < 32; ++j) rrow[j] = 0.0f;
        for (int k = 0; k < D; ++k) {
            float bv = brow[k];
            #pragma unroll
            for (int t = 0; t < 8; ++t) {
                float4 q = *(const float4*)&Q[k * DQ + c0 + 4 * t];
                rrow[4*t+0] = fmaf(bv, q.x, rrow[4*t+0]);
                rrow[4*t+1] = fmaf(bv, q.y, rrow[4*t+1]);
                rrow[4*t+2] = fmaf(bv, q.z, rrow[4*t+2]);
                rrow[4*t+3] = fmaf(bv, q.w, rrow[4*t+3]);
            }
        }
        __syncthreads();
        #pragma unroll
        for (int t = 0; t < 8; ++t)
            *(float4*)&Q[i * DQ + c0 + 4 * t] =
                make_float4(rrow[4*t+0], rrow[4*t+1], rrow[4*t+2], rrow[4*t+3]);
        __syncthreads();
    }

    float* om = out + (size_t)m * DD + i * D + c0;
    #pragma unroll
    for (int t = 0; t < 8; ++t) {
        float4 v = *(const float4*)&Q[i * DQ + c0 + 4 * t];
        *(float4*)&om[4 * t] = v;
    }
}

// ========================================================================
extern "C" void kernel_launch(void* const* d_in, const int* in_sizes, int n_in,
                              void* d_out, int out_size) {
    const float* X  = (const float*)d_in[0];
    const float* bw = (const float*)d_in[1];
    float* out = (float*)d_out;

    onesided_log_kernel<<<NMAT, 64>>>(X);
    gram_kernel<<<dim3(4, 4, 8), 256>>>();
    w_kernel<<<NMAT, 256>>>(bw);
    colsum_kernel<<<8, 256>>>();
    ms_kernel<<<dim3(64, 4), 256>>>();
    expm_kernel<<<NMAT, 128>>>(out);
}